// round 7
// baseline (speedup 1.0000x reference)
#include <cuda_runtime.h>
#include <cuda_bf16.h>

// out[row] = (sum over 1024 elements of x[row,:]) * sum(coeffs)
// Persistent grid: 148 SMs x 12 CTAs, each warp grid-strides over rows.
// Per row: 32 lanes x 8 front-batched float4 loads, warp-shuffle reduce.
// 1-row (4KB) work granularity kills the wave-quantization tail.
__global__ void __launch_bounds__(256, 12) spline_rowsum_persist_kernel(
        const float* __restrict__ x,
        const float* __restrict__ coeffs,
        int ncoef,
        int rows,
        float* __restrict__ out) {
    const int warps_total = (gridDim.x * blockDim.x) >> 5;
    const int warp_id     = (blockIdx.x * (blockDim.x >> 5)) + (threadIdx.x >> 5);
    const int lane        = threadIdx.x & 31;

    // coeff sum once per thread (10 elems, L2-resident after first blocks)
    float cs = 0.0f;
    for (int i = 0; i < ncoef; i++) cs += coeffs[i];

    for (int row = warp_id; row < rows; row += warps_total) {
        const float4* __restrict__ p =
            reinterpret_cast<const float4*>(x) + (size_t)row * 256 + lane;

        // 8 independent 16B loads, front-batched
        float4 v0 = p[0 * 32];
        float4 v1 = p[1 * 32];
        float4 v2 = p[2 * 32];
        float4 v3 = p[3 * 32];
        float4 v4 = p[4 * 32];
        float4 v5 = p[5 * 32];
        float4 v6 = p[6 * 32];
        float4 v7 = p[7 * 32];

        float s0 = (v0.x + v0.y) + (v0.z + v0.w);
        float s1 = (v1.x + v1.y) + (v1.z + v1.w);
        float s2 = (v2.x + v2.y) + (v2.z + v2.w);
        float s3 = (v3.x + v3.y) + (v3.z + v3.w);
        float s4 = (v4.x + v4.y) + (v4.z + v4.w);
        float s5 = (v5.x + v5.y) + (v5.z + v5.w);
        float s6 = (v6.x + v6.y) + (v6.z + v6.w);
        float s7 = (v7.x + v7.y) + (v7.z + v7.w);

        float s = ((s0 + s1) + (s2 + s3)) + ((s4 + s5) + (s6 + s7));

        #pragma unroll
        for (int o = 16; o > 0; o >>= 1)
            s += __shfl_xor_sync(0xffffffffu, s, o);

        if (lane == 0)
            out[row] = s * cs;
    }
}

extern "C" void kernel_launch(void* const* d_in, const int* in_sizes, int n_in,
                              void* d_out, int out_size) {
    const float* x      = (const float*)d_in[0];
    const float* coeffs = (const float*)d_in[1];
    float*       out    = (float*)d_out;

    const int rows  = out_size;            // 65536
    const int ncoef = in_sizes[1];         // 10

    // GB300: 152 SMs; 12 CTAs/SM at ~40 regs. Exact-fill persistent grid.
    const int blocks = 152 * 12;           // 1824
    spline_rowsum_persist_kernel<<<blocks, 256>>>(x, coeffs, ncoef, rows, out);
}

// round 8
// speedup vs baseline: 1.0195x; 1.0195x over previous
#include <cuda_runtime.h>
#include <cuda_bf16.h>

// out[row] = (sum over 1024 elements of x[row,:]) * sum(coeffs)
// One warp per row. Blackwell 256-bit loads: 4 x ld.global.nc.v8.f32 per lane
// (front-batched, 32B each, fully coalesced 1KB/warp/instr), shuffle reduce.
__global__ void __launch_bounds__(256, 6) spline_rowsum_v8_kernel(
        const float* __restrict__ x,
        const float* __restrict__ coeffs,
        int ncoef,
        float* __restrict__ out) {
    const int row  = (blockIdx.x * (blockDim.x >> 5)) + (threadIdx.x >> 5);
    const int lane = threadIdx.x & 31;

    // lane handles 4 chunks of 8 consecutive floats: offsets 0,256,512,768
    const float* __restrict__ p = x + (size_t)row * 1024 + lane * 8;

    float a0, a1, a2, a3, a4, a5, a6, a7;
    float b0, b1, b2, b3, b4, b5, b6, b7;
    float c0, c1, c2, c3, c4, c5, c6, c7;
    float d0, d1, d2, d3, d4, d5, d6, d7;

    asm volatile("ld.global.nc.v8.f32 {%0,%1,%2,%3,%4,%5,%6,%7}, [%8];"
        : "=f"(a0),"=f"(a1),"=f"(a2),"=f"(a3),"=f"(a4),"=f"(a5),"=f"(a6),"=f"(a7)
        : "l"(p));
    asm volatile("ld.global.nc.v8.f32 {%0,%1,%2,%3,%4,%5,%6,%7}, [%8];"
        : "=f"(b0),"=f"(b1),"=f"(b2),"=f"(b3),"=f"(b4),"=f"(b5),"=f"(b6),"=f"(b7)
        : "l"(p + 256));
    asm volatile("ld.global.nc.v8.f32 {%0,%1,%2,%3,%4,%5,%6,%7}, [%8];"
        : "=f"(c0),"=f"(c1),"=f"(c2),"=f"(c3),"=f"(c4),"=f"(c5),"=f"(c6),"=f"(c7)
        : "l"(p + 512));
    asm volatile("ld.global.nc.v8.f32 {%0,%1,%2,%3,%4,%5,%6,%7}, [%8];"
        : "=f"(d0),"=f"(d1),"=f"(d2),"=f"(d3),"=f"(d4),"=f"(d5),"=f"(d6),"=f"(d7)
        : "l"(p + 768));

    float sa = ((a0 + a1) + (a2 + a3)) + ((a4 + a5) + (a6 + a7));
    float sb = ((b0 + b1) + (b2 + b3)) + ((b4 + b5) + (b6 + b7));
    float sc = ((c0 + c1) + (c2 + c3)) + ((c4 + c5) + (c6 + c7));
    float sd = ((d0 + d1) + (d2 + d3)) + ((d4 + d5) + (d6 + d7));

    float s = (sa + sb) + (sc + sd);

    #pragma unroll
    for (int o = 16; o > 0; o >>= 1)
        s += __shfl_xor_sync(0xffffffffu, s, o);

    if (lane == 0) {
        float cs = 0.0f;
        for (int i = 0; i < ncoef; i++) cs += coeffs[i];  // 10 elems, L2-hit
        out[row] = s * cs;
    }
}

extern "C" void kernel_launch(void* const* d_in, const int* in_sizes, int n_in,
                              void* d_out, int out_size) {
    const float* x      = (const float*)d_in[0];
    const float* coeffs = (const float*)d_in[1];
    float*       out    = (float*)d_out;

    const int rows  = out_size;            // 65536
    const int ncoef = in_sizes[1];         // 10

    const int warps_per_block = 8;         // 256 threads
    const int blocks = rows / warps_per_block;  // 8192
    spline_rowsum_v8_kernel<<<blocks, 256>>>(x, coeffs, ncoef, out);
}

// round 9
// speedup vs baseline: 1.0429x; 1.0230x over previous
#include <cuda_runtime.h>
#include <cuda_bf16.h>

// out[row] = (sum over 1024 elements of x[row,:]) * sum(coeffs)
// One warp per row: 32 lanes x 8 front-batched float4 streaming loads
// (true MLP=8 per thread), warp-shuffle reduce, streaming store.
// Best-of-family: ncu dur 41.25us, DRAM ~83.5% (= achieved HBM ceiling).
__global__ void __launch_bounds__(256, 6) spline_rowsum_final_kernel(
        const float* __restrict__ x,
        const float* __restrict__ coeffs,
        int ncoef,
        float* __restrict__ out) {
    const int row  = (blockIdx.x * (blockDim.x >> 5)) + (threadIdx.x >> 5);
    const int lane = threadIdx.x & 31;

    const float4* __restrict__ xp =
        reinterpret_cast<const float4*>(x) + (size_t)row * 256 + lane;

    // 8 independent 16B loads per lane — all issued before any consumption
    float4 v0 = __ldcs(xp + 0 * 32);
    float4 v1 = __ldcs(xp + 1 * 32);
    float4 v2 = __ldcs(xp + 2 * 32);
    float4 v3 = __ldcs(xp + 3 * 32);
    float4 v4 = __ldcs(xp + 4 * 32);
    float4 v5 = __ldcs(xp + 5 * 32);
    float4 v6 = __ldcs(xp + 6 * 32);
    float4 v7 = __ldcs(xp + 7 * 32);

    float s0 = (v0.x + v0.y) + (v0.z + v0.w);
    float s1 = (v1.x + v1.y) + (v1.z + v1.w);
    float s2 = (v2.x + v2.y) + (v2.z + v2.w);
    float s3 = (v3.x + v3.y) + (v3.z + v3.w);
    float s4 = (v4.x + v4.y) + (v4.z + v4.w);
    float s5 = (v5.x + v5.y) + (v5.z + v5.w);
    float s6 = (v6.x + v6.y) + (v6.z + v6.w);
    float s7 = (v7.x + v7.y) + (v7.z + v7.w);

    float s = ((s0 + s1) + (s2 + s3)) + ((s4 + s5) + (s6 + s7));

    #pragma unroll
    for (int o = 16; o > 0; o >>= 1)
        s += __shfl_xor_sync(0xffffffffu, s, o);

    if (lane == 0) {
        float cs = 0.0f;
        for (int i = 0; i < ncoef; i++) cs += coeffs[i];  // 10 elems, L2-hit
        __stcs(out + row, s * cs);
    }
}

extern "C" void kernel_launch(void* const* d_in, const int* in_sizes, int n_in,
                              void* d_out, int out_size) {
    const float* x      = (const float*)d_in[0];
    const float* coeffs = (const float*)d_in[1];
    float*       out    = (float*)d_out;

    const int rows  = out_size;            // 65536 (divisible by 8)
    const int ncoef = in_sizes[1];         // 10

    const int warps_per_block = 8;         // 256 threads
    const int blocks = rows / warps_per_block;  // 8192
    spline_rowsum_final_kernel<<<blocks, 256>>>(x, coeffs, ncoef, out);
}

// round 10
// speedup vs baseline: 1.0502x; 1.0069x over previous
#include <cuda_runtime.h>
#include <cuda_bf16.h>

// out[row] = (sum over 1024 elements of x[row,:]) * sum(coeffs)
// One warp per row: 32 lanes x 8 front-batched float4 streaming loads
// (MLP=8/thread), warp-shuffle reduce, streaming store.
// Coeff sum hoisted to the top (lane 0) so its L2 latency hides under the
// outstanding row loads instead of sitting exposed in the tail.
__global__ void __launch_bounds__(256, 6) spline_rowsum_final2_kernel(
        const float* __restrict__ x,
        const float* __restrict__ coeffs,
        int ncoef,
        float* __restrict__ out) {
    const int row  = (blockIdx.x * (blockDim.x >> 5)) + (threadIdx.x >> 5);
    const int lane = threadIdx.x & 31;

    // Issue coeff loads FIRST (lane 0 only, uniform addr, L2-resident):
    // their latency overlaps the row-load burst below.
    float cs = 0.0f;
    if (lane == 0) {
        #pragma unroll 2
        for (int i = 0; i < ncoef; i++) cs += __ldg(coeffs + i);
    }

    const float4* __restrict__ xp =
        reinterpret_cast<const float4*>(x) + (size_t)row * 256 + lane;

    // 8 independent 16B streaming loads per lane — all issued up front
    float4 v0 = __ldcs(xp + 0 * 32);
    float4 v1 = __ldcs(xp + 1 * 32);
    float4 v2 = __ldcs(xp + 2 * 32);
    float4 v3 = __ldcs(xp + 3 * 32);
    float4 v4 = __ldcs(xp + 4 * 32);
    float4 v5 = __ldcs(xp + 5 * 32);
    float4 v6 = __ldcs(xp + 6 * 32);
    float4 v7 = __ldcs(xp + 7 * 32);

    float s0 = (v0.x + v0.y) + (v0.z + v0.w);
    float s1 = (v1.x + v1.y) + (v1.z + v1.w);
    float s2 = (v2.x + v2.y) + (v2.z + v2.w);
    float s3 = (v3.x + v3.y) + (v3.z + v3.w);
    float s4 = (v4.x + v4.y) + (v4.z + v4.w);
    float s5 = (v5.x + v5.y) + (v5.z + v5.w);
    float s6 = (v6.x + v6.y) + (v6.z + v6.w);
    float s7 = (v7.x + v7.y) + (v7.z + v7.w);

    float s = ((s0 + s1) + (s2 + s3)) + ((s4 + s5) + (s6 + s7));

    #pragma unroll
    for (int o = 16; o > 0; o >>= 1)
        s += __shfl_xor_sync(0xffffffffu, s, o);

    if (lane == 0)
        __stcs(out + row, s * cs);
}

extern "C" void kernel_launch(void* const* d_in, const int* in_sizes, int n_in,
                              void* d_out, int out_size) {
    const float* x      = (const float*)d_in[0];
    const float* coeffs = (const float*)d_in[1];
    float*       out    = (float*)d_out;

    const int rows  = out_size;            // 65536 (divisible by 8)
    const int ncoef = in_sizes[1];         // 10

    const int warps_per_block = 8;         // 256 threads
    const int blocks = rows / warps_per_block;  // 8192
    spline_rowsum_final2_kernel<<<blocks, 256>>>(x, coeffs, ncoef, out);
}